// round 1
// baseline (speedup 1.0000x reference)
#include <cuda_runtime.h>
#include <cuda_bf16.h>

// Problem constants (from reference setup_inputs)
#define NMAX 50000
#define EMAX 200000
#define SDIM 16
#define FDIM 32
// z row stride: S*F = 512 floats per node

// Scratch (static __device__ allocation — allowed; runtime alloc is not)
__device__ float g_Z[(size_t)NMAX * 512];   // 102.4 MB: z[n, s*32+o]
__device__ float g_xb[(size_t)NMAX * 32];   // bias-path per node
__device__ float g_agg[(size_t)NMAX * 32];  // scatter target
__device__ float g_h[(size_t)NMAX * 32];    // layer output

// ---------------------------------------------------------------------------
// Z[n, s*32+o] = sum_f x[n,f] * W[s*1024 + f*32 + o]
// Block = 256 threads, 16 nodes per block. Each thread owns output columns
// j = tid (s0 = tid>>5 in 0..7) and j+256 (s0+8); holds the two W columns in
// 64 registers, streams x rows from smem via float4 broadcast.
// ---------------------------------------------------------------------------
__global__ __launch_bounds__(256) void fgn_gemm_kernel(
    const float* __restrict__ xext, const float* __restrict__ w,
    int N, int use_gh) {
  const float* x = use_gh ? g_h : xext;
  __shared__ __align__(16) float xs[16 * 32];
  const int tid = threadIdx.x;
  const int n0 = blockIdx.x * 16;

  // load x tile (coalesced)
  for (int i = tid; i < 16 * 32; i += 256) {
    int n = n0 + (i >> 5);
    xs[i] = (n < N) ? x[(size_t)n * 32 + (i & 31)] : 0.f;
  }

  const int o0 = tid & 31;
  const int s0 = tid >> 5;
  float w0[32], w1[32];
#pragma unroll
  for (int f = 0; f < 32; f++) {
    w0[f] = w[s0 * 1024 + f * 32 + o0];
    w1[f] = w[(s0 + 8) * 1024 + f * 32 + o0];
  }
  __syncthreads();

  const int nend = min(16, N - n0);
  for (int nb = 0; nb < nend; nb++) {
    const float4* xv4 = (const float4*)(xs + nb * 32);
    float a0 = 0.f, a1 = 0.f;
#pragma unroll
    for (int q = 0; q < 8; q++) {
      float4 v = xv4[q];
      a0 += v.x * w0[4 * q + 0] + v.y * w0[4 * q + 1] +
            v.z * w0[4 * q + 2] + v.w * w0[4 * q + 3];
      a1 += v.x * w1[4 * q + 0] + v.y * w1[4 * q + 1] +
            v.z * w1[4 * q + 2] + v.w * w1[4 * q + 3];
    }
    size_t base = (size_t)(n0 + nb) * 512;
    g_Z[base + s0 * 32 + o0] = a0;
    g_Z[base + (s0 + 8) * 32 + o0] = a1;
  }
}

// ---------------------------------------------------------------------------
// xb[n,o] = sum_f x[n,f] * B[f*32+o]   (warp per node, m in smem)
// ---------------------------------------------------------------------------
__global__ __launch_bounds__(256) void xb_kernel(
    const float* __restrict__ xext, const float* __restrict__ m,
    int N, int use_gh) {
  const float* x = use_gh ? g_h : xext;
  __shared__ float ms[1024];
  for (int i = threadIdx.x; i < 1024; i += 256) ms[i] = m[i];
  __syncthreads();
  int warp = (blockIdx.x * 256 + threadIdx.x) >> 5;
  int lane = threadIdx.x & 31;
  if (warp >= N) return;
  float xv = x[(size_t)warp * 32 + lane];
  float acc = 0.f;
#pragma unroll
  for (int f = 0; f < 32; f++)
    acc += __shfl_sync(0xffffffffu, xv, f) * ms[f * 32 + lane];
  g_xb[(size_t)warp * 32 + lane] = acc;
}

// ---------------------------------------------------------------------------
// zero the scatter accumulator
// ---------------------------------------------------------------------------
__global__ void zero_agg_kernel(int total) {
  for (int i = blockIdx.x * blockDim.x + threadIdx.x; i < total;
       i += gridDim.x * blockDim.x)
    g_agg[i] = 0.f;
}

// ---------------------------------------------------------------------------
// Per-edge: m[o] = xb[src,o] + sum_s e[ed,s] * z[src, s*32+o]; scatter to dst.
// Warp per edge, lane = output channel o. z reads are 128B-coalesced.
// ---------------------------------------------------------------------------
__global__ __launch_bounds__(256) void edge_kernel(
    const float* __restrict__ e, const int* __restrict__ src,
    const int* __restrict__ dst, int E) {
  int warp = (blockIdx.x * 256 + threadIdx.x) >> 5;
  int lane = threadIdx.x & 31;
  if (warp >= E) return;
  int sn = src[warp];
  int dn = dst[warp];
  float ev = (lane < SDIM) ? e[(size_t)warp * SDIM + lane] : 0.f;
  const float* zp = g_Z + (size_t)sn * 512;
  float acc = g_xb[(size_t)sn * 32 + lane];
#pragma unroll
  for (int s = 0; s < SDIM; s++) {
    float es = __shfl_sync(0xffffffffu, ev, s);
    acc += es * zp[s * 32 + lane];
  }
  atomicAdd(&g_agg[(size_t)dn * 32 + lane], acc);  // emitted as RED (no return)
}

// ---------------------------------------------------------------------------
// h[n] = relu(agg[n] + x[n] @ root + bias). Warp per node. In-place safe
// for layer 2 (row fully read before written).
// ---------------------------------------------------------------------------
__global__ __launch_bounds__(256) void node_update_kernel(
    const float* __restrict__ xext, const float* __restrict__ root,
    const float* __restrict__ bias, int N, int use_gh) {
  const float* x = use_gh ? g_h : xext;
  __shared__ float ms[1024];
  __shared__ float bs[32];
  for (int i = threadIdx.x; i < 1024; i += 256) ms[i] = root[i];
  if (threadIdx.x < 32) bs[threadIdx.x] = bias[threadIdx.x];
  __syncthreads();
  int warp = (blockIdx.x * 256 + threadIdx.x) >> 5;
  int lane = threadIdx.x & 31;
  if (warp >= N) return;
  float xv = x[(size_t)warp * 32 + lane];
  float acc = g_agg[(size_t)warp * 32 + lane] + bs[lane];
#pragma unroll
  for (int f = 0; f < 32; f++)
    acc += __shfl_sync(0xffffffffu, xv, f) * ms[f * 32 + lane];
  g_h[(size_t)warp * 32 + lane] = fmaxf(acc, 0.f);
}

// ---------------------------------------------------------------------------
// out[0] = dense_b[0]  (d_out is poisoned; pool atomicAdds on top)
// ---------------------------------------------------------------------------
__global__ void init_out_kernel(const float* __restrict__ db,
                                float* __restrict__ out) {
  out[0] = db[0];
}

// out[0] += sum_n sum_o h[n,o]*dense_w[o]
__global__ __launch_bounds__(256) void pool_kernel(
    const float* __restrict__ dw, float* __restrict__ out, int N) {
  int lane = threadIdx.x & 31;
  int warp = (blockIdx.x * 256 + threadIdx.x) >> 5;
  int nwarps = (gridDim.x * 256) >> 5;
  float wv = dw[lane];
  float acc = 0.f;
  for (int n = warp; n < N; n += nwarps)
    acc += g_h[(size_t)n * 32 + lane] * wv;
#pragma unroll
  for (int off = 16; off; off >>= 1)
    acc += __shfl_down_sync(0xffffffffu, acc, off);
  if (lane == 0) atomicAdd(out, acc);
}

// ---------------------------------------------------------------------------
extern "C" void kernel_launch(void* const* d_in, const int* in_sizes, int n_in,
                              void* d_out, int out_size) {
  const float* x   = (const float*)d_in[0];
  const float* e   = (const float*)d_in[1];
  const int*   src = (const int*)d_in[2];
  const int*   dst = (const int*)d_in[3];
  const float* fw1 = (const float*)d_in[4];
  const float* fb1 = (const float*)d_in[5];
  const float* r1  = (const float*)d_in[6];
  const float* b1  = (const float*)d_in[7];
  const float* fw2 = (const float*)d_in[8];
  const float* fb2 = (const float*)d_in[9];
  const float* r2  = (const float*)d_in[10];
  const float* b2  = (const float*)d_in[11];
  const float* dw  = (const float*)d_in[12];
  const float* db  = (const float*)d_in[13];
  float* out = (float*)d_out;

  int N = in_sizes[0] / FDIM;
  int E = in_sizes[2];
  if (N > NMAX) N = NMAX;
  if (E > EMAX) E = EMAX;

  int gemm_grid   = (N + 15) / 16;
  int warp_grid_N = (N + 7) / 8;   // 8 warps / 256-thread block
  int warp_grid_E = (E + 7) / 8;
  int zero_total  = N * 32;
  int zero_grid   = (zero_total + 1023) / 1024;

  // ----- layer 1 -----
  fgn_gemm_kernel<<<gemm_grid, 256>>>(x, fw1, N, 0);
  xb_kernel<<<warp_grid_N, 256>>>(x, fb1, N, 0);
  zero_agg_kernel<<<zero_grid, 256>>>(zero_total);
  edge_kernel<<<warp_grid_E, 256>>>(e, src, dst, E);
  node_update_kernel<<<warp_grid_N, 256>>>(x, r1, b1, N, 0);

  // ----- layer 2 (reads/writes g_h) -----
  fgn_gemm_kernel<<<gemm_grid, 256>>>(nullptr, fw2, N, 1);
  xb_kernel<<<warp_grid_N, 256>>>(nullptr, fb2, N, 1);
  zero_agg_kernel<<<zero_grid, 256>>>(zero_total);
  edge_kernel<<<warp_grid_E, 256>>>(e, src, dst, E);
  node_update_kernel<<<warp_grid_N, 256>>>(nullptr, r2, b2, N, 1);

  // ----- global sum pool + dense -----
  init_out_kernel<<<1, 1>>>(db, out);
  pool_kernel<<<296, 256>>>(dw, out, N);
}

// round 9
// speedup vs baseline: 1.0196x; 1.0196x over previous
#include <cuda_runtime.h>

#define NMAX 50000
#define EMAX 200000
#define SDIM 16
#define FDIM 32

// Static device scratch (zero-initialized at module load; invariants below
// keep g_agg zero at every kernel_launch entry).
__device__ float g_Z[(size_t)NMAX * 512];   // z[n, s*32+o]
__device__ float g_xb[(size_t)NMAX * 32];   // bias-path per node
__device__ float g_agg[(size_t)NMAX * 32];  // scatter target (zero at entry)
__device__ float g_h[(size_t)NMAX * 32];    // layer-1 output
__device__ int   g_deg[NMAX];
__device__ int   g_off[NMAX + 1];
__device__ int   g_cur[NMAX];
__device__ int   g_bsum[256];               // block partials for scan (<=196 used)
__device__ int   g_eidx[EMAX];              // edges sorted by src

// ---------------------------------------------------------------------------
// CSR build: zero degrees, histogram, 3-step scan, scatter permutation
// ---------------------------------------------------------------------------
__global__ void zero_deg_kernel(int N) {
  int i = blockIdx.x * blockDim.x + threadIdx.x;
  if (i < N) g_deg[i] = 0;
}

__global__ void hist_kernel(const int* __restrict__ src, int E) {
  int i = blockIdx.x * blockDim.x + threadIdx.x;
  if (i < E) atomicAdd(&g_deg[src[i]], 1);
}

__global__ __launch_bounds__(256) void scan1_kernel(int N) {
  __shared__ int sm[256];
  int i = blockIdx.x * 256 + threadIdx.x;
  int v = (i < N) ? g_deg[i] : 0;
  sm[threadIdx.x] = v;
  __syncthreads();
#pragma unroll
  for (int d = 1; d < 256; d <<= 1) {
    int t = (threadIdx.x >= d) ? sm[threadIdx.x - d] : 0;
    __syncthreads();
    sm[threadIdx.x] += t;
    __syncthreads();
  }
  if (i < N) g_off[i] = sm[threadIdx.x] - v;  // exclusive within block
  if (threadIdx.x == 255) g_bsum[blockIdx.x] = sm[255];
}

__global__ __launch_bounds__(256) void scan2_kernel(int nb) {
  __shared__ int sm[256];
  int v = (threadIdx.x < nb) ? g_bsum[threadIdx.x] : 0;
  sm[threadIdx.x] = v;
  __syncthreads();
#pragma unroll
  for (int d = 1; d < 256; d <<= 1) {
    int t = (threadIdx.x >= d) ? sm[threadIdx.x - d] : 0;
    __syncthreads();
    sm[threadIdx.x] += t;
    __syncthreads();
  }
  g_bsum[threadIdx.x] = sm[threadIdx.x] - v;  // exclusive block offsets
}

__global__ void scan3_kernel(int N, int E) {
  int i = blockIdx.x * blockDim.x + threadIdx.x;
  if (i < N) {
    int o = g_off[i] + g_bsum[i >> 8];
    g_off[i] = o;
    g_cur[i] = o;
  }
  if (i == 0) g_off[N] = E;
}

__global__ void scatter_kernel(const int* __restrict__ src, int E) {
  int i = blockIdx.x * blockDim.x + threadIdx.x;
  if (i >= E) return;
  int pos = atomicAdd(&g_cur[src[i]], 1);
  g_eidx[pos] = i;
}

// ---------------------------------------------------------------------------
// Z[n, s*32+o] = sum_f x[n,f] * W[s*1024 + f*32 + o], plus (warp 0 only)
// xb[n,o] = sum_f x[n,f] * B[f*32+o].
// 16 nodes/block; thread (s0,o0) owns Z columns (s0,o0) and (s0+8,o0),
// packed as f32x2 so the inner loop is 32 FFMA2 instead of 64 FFMA.
// ---------------------------------------------------------------------------
__global__ __launch_bounds__(256) void fgn_gemm_kernel(
    const float* __restrict__ xext, const float* __restrict__ w,
    const float* __restrict__ bvec, int N, int use_gh) {
  const float* x = use_gh ? g_h : xext;
  __shared__ __align__(16) float xs[16 * 32];
  const int tid = threadIdx.x;
  const int n0 = blockIdx.x * 16;

  for (int i = tid; i < 16 * 32; i += 256) {
    int n = n0 + (i >> 5);
    xs[i] = (n < N) ? x[(size_t)n * 32 + (i & 31)] : 0.f;
  }

  const int o0 = tid & 31;
  const int s0 = tid >> 5;
  unsigned long long wp[32];
#pragma unroll
  for (int f = 0; f < 32; f++) {
    float lo = w[s0 * 1024 + f * 32 + o0];
    float hi = w[(s0 + 8) * 1024 + f * 32 + o0];
    asm("mov.b64 %0, {%1, %2};" : "=l"(wp[f]) : "f"(lo), "f"(hi));
  }
  float bcol[32];
  if (s0 == 0) {
#pragma unroll
    for (int f = 0; f < 32; f++) bcol[f] = bvec[f * 32 + o0];
  }
  __syncthreads();

  const int nend = min(16, N - n0);
  for (int nb = 0; nb < nend; nb++) {
    const float4* xv4 = (const float4*)(xs + nb * 32);
    unsigned long long acc = 0ull;  // (0.f, 0.f)
    float accb = 0.f;
#pragma unroll
    for (int q = 0; q < 8; q++) {
      float4 v = xv4[q];
      unsigned long long xx;
      asm("mov.b64 %0, {%1, %1};" : "=l"(xx) : "f"(v.x));
      asm("fma.rn.f32x2 %0, %1, %2, %0;" : "+l"(acc) : "l"(xx), "l"(wp[4 * q + 0]));
      asm("mov.b64 %0, {%1, %1};" : "=l"(xx) : "f"(v.y));
      asm("fma.rn.f32x2 %0, %1, %2, %0;" : "+l"(acc) : "l"(xx), "l"(wp[4 * q + 1]));
      asm("mov.b64 %0, {%1, %1};" : "=l"(xx) : "f"(v.z));
      asm("fma.rn.f32x2 %0, %1, %2, %0;" : "+l"(acc) : "l"(xx), "l"(wp[4 * q + 2]));
      asm("mov.b64 %0, {%1, %1};" : "=l"(xx) : "f"(v.w));
      asm("fma.rn.f32x2 %0, %1, %2, %0;" : "+l"(acc) : "l"(xx), "l"(wp[4 * q + 3]));
      if (s0 == 0) {
        accb += v.x * bcol[4 * q + 0] + v.y * bcol[4 * q + 1] +
                v.z * bcol[4 * q + 2] + v.w * bcol[4 * q + 3];
      }
    }
    float a0, a1;
    asm("mov.b64 {%0, %1}, %2;" : "=f"(a0), "=f"(a1) : "l"(acc));
    size_t base = (size_t)(n0 + nb) * 512;
    g_Z[base + s0 * 32 + o0] = a0;
    g_Z[base + (s0 + 8) * 32 + o0] = a1;
    if (s0 == 0) g_xb[(size_t)(n0 + nb) * 32 + o0] = accb;
  }
}

// ---------------------------------------------------------------------------
// Node-centric edge contraction: warp per src node, Z row resident in regs.
// For each out-edge: m[o] = xb[n,o] + sum_s e[ed,s]*z[s,o]; RED into agg[dst].
// ---------------------------------------------------------------------------
__global__ __launch_bounds__(256) void edge_csr_kernel(
    const float* __restrict__ e, const int* __restrict__ dst, int N) {
  int n = (blockIdx.x * 256 + threadIdx.x) >> 5;
  int lane = threadIdx.x & 31;
  if (n >= N) return;
  int beg = g_off[n], end = g_off[n + 1];
  if (beg == end) return;

  const float* zp = g_Z + (size_t)n * 512;
  float z[16];
#pragma unroll
  for (int s = 0; s < 16; s++) z[s] = zp[s * 32 + lane];
  float xbv = g_xb[(size_t)n * 32 + lane];

  for (int j = beg; j < end; j++) {
    int eid = g_eidx[j];
    float ev = (lane < SDIM) ? e[(size_t)eid * SDIM + lane] : 0.f;
    int dn = dst[eid];
    float acc = xbv;
#pragma unroll
    for (int s = 0; s < 16; s++)
      acc += __shfl_sync(0xffffffffu, ev, s) * z[s];
    atomicAdd(&g_agg[(size_t)dn * 32 + lane], acc);
  }
}

// ---------------------------------------------------------------------------
// Layer-1 node update: h = relu(agg + x@root + bias); re-zero agg (invariant).
// ---------------------------------------------------------------------------
__global__ __launch_bounds__(256) void node_update1_kernel(
    const float* __restrict__ x, const float* __restrict__ root,
    const float* __restrict__ bias, int N) {
  __shared__ float ms[1024];
  __shared__ float bs[32];
  for (int i = threadIdx.x; i < 1024; i += 256) ms[i] = root[i];
  if (threadIdx.x < 32) bs[threadIdx.x] = bias[threadIdx.x];
  __syncthreads();
  int n = (blockIdx.x * 256 + threadIdx.x) >> 5;
  int lane = threadIdx.x & 31;
  if (n >= N) return;
  size_t idx = (size_t)n * 32 + lane;
  float xv = x[idx];
  float acc = g_agg[idx] + bs[lane];
  g_agg[idx] = 0.f;  // restore invariant for next layer
#pragma unroll
  for (int f = 0; f < 32; f++)
    acc += __shfl_sync(0xffffffffu, xv, f) * ms[f * 32 + lane];
  g_h[idx] = fmaxf(acc, 0.f);
}

// ---------------------------------------------------------------------------
// out[0] = dense_b[0] (run before node_update2's atomics)
// ---------------------------------------------------------------------------
__global__ void init_out_kernel(const float* __restrict__ db,
                                float* __restrict__ out) {
  out[0] = db[0];
}

// ---------------------------------------------------------------------------
// Layer-2 node update fused with global pool + dense:
// h2 = relu(agg + h@root + bias); out += sum_n h2[n,:]·dw. Re-zero agg.
// Block-level reduction -> one atomic per block.
// ---------------------------------------------------------------------------
__global__ __launch_bounds__(256) void node_update2_kernel(
    const float* __restrict__ root, const float* __restrict__ bias,
    const float* __restrict__ dw, float* __restrict__ out, int N) {
  __shared__ float ms[1024];
  __shared__ float bs[32];
  __shared__ float part[8];
  for (int i = threadIdx.x; i < 1024; i += 256) ms[i] = root[i];
  if (threadIdx.x < 32) bs[threadIdx.x] = bias[threadIdx.x];
  __syncthreads();
  int n = (blockIdx.x * 256 + threadIdx.x) >> 5;
  int lane = threadIdx.x & 31;
  int wid = threadIdx.x >> 5;
  float contrib = 0.f;
  if (n < N) {
    size_t idx = (size_t)n * 32 + lane;
    float xv = g_h[idx];
    float acc = g_agg[idx] + bs[lane];
    g_agg[idx] = 0.f;  // restore invariant for next call
#pragma unroll
    for (int f = 0; f < 32; f++)
      acc += __shfl_sync(0xffffffffu, xv, f) * ms[f * 32 + lane];
    contrib = fmaxf(acc, 0.f) * dw[lane];
  }
#pragma unroll
  for (int off = 16; off; off >>= 1)
    contrib += __shfl_down_sync(0xffffffffu, contrib, off);
  if (lane == 0) part[wid] = contrib;
  __syncthreads();
  if (threadIdx.x == 0) {
    float s = 0.f;
#pragma unroll
    for (int w = 0; w < 8; w++) s += part[w];
    atomicAdd(out, s);
  }
}

// ---------------------------------------------------------------------------
extern "C" void kernel_launch(void* const* d_in, const int* in_sizes, int n_in,
                              void* d_out, int out_size) {
  const float* x   = (const float*)d_in[0];
  const float* e   = (const float*)d_in[1];
  const int*   src = (const int*)d_in[2];
  const int*   dst = (const int*)d_in[3];
  const float* fw1 = (const float*)d_in[4];
  const float* fb1 = (const float*)d_in[5];
  const float* r1  = (const float*)d_in[6];
  const float* b1  = (const float*)d_in[7];
  const float* fw2 = (const float*)d_in[8];
  const float* fb2 = (const float*)d_in[9];
  const float* r2  = (const float*)d_in[10];
  const float* b2  = (const float*)d_in[11];
  const float* dw  = (const float*)d_in[12];
  const float* db  = (const float*)d_in[13];
  float* out = (float*)d_out;

  int N = in_sizes[0] / FDIM;
  int E = in_sizes[2];
  if (N > NMAX) N = NMAX;
  if (E > EMAX) E = EMAX;

  int gN256  = (N + 255) / 256;
  int gE256  = (E + 255) / 256;
  int gemm_g = (N + 15) / 16;
  int warpN  = (N + 7) / 8;

  // ----- CSR build (src-sorted edge permutation) -----
  zero_deg_kernel<<<gN256, 256>>>(N);
  hist_kernel<<<gE256, 256>>>(src, E);
  scan1_kernel<<<gN256, 256>>>(N);
  scan2_kernel<<<1, 256>>>(gN256);
  scan3_kernel<<<gN256, 256>>>(N, E);
  scatter_kernel<<<gE256, 256>>>(src, E);

  // ----- layer 1 -----
  fgn_gemm_kernel<<<gemm_g, 256>>>(x, fw1, fb1, N, 0);
  edge_csr_kernel<<<warpN, 256>>>(e, dst, N);
  node_update1_kernel<<<warpN, 256>>>(x, r1, b1, N);

  // ----- layer 2 -----
  fgn_gemm_kernel<<<gemm_g, 256>>>(nullptr, fw2, fb2, N, 1);
  edge_csr_kernel<<<warpN, 256>>>(e, dst, N);
  init_out_kernel<<<1, 1>>>(db, out);
  node_update2_kernel<<<warpN, 256>>>(r2, b2, dw, out, N);
}